// round 15
// baseline (speedup 1.0000x reference)
#include <cuda_runtime.h>
#include <cuda_bf16.h>

#define BATCH 8192
#define T 50
#define F 17
#define HID 64
#define BT 64
#define NB (BATCH/BT)   // 128 blocks
#define NTHREADS 512
#define NW 16
#define BSTR 240        // bytes per bf16-tile row
#define ABUF_SZ 30720   // one A buffer: hi(15360) + lo(15360)

// k layout of A / gates-B: [h 0..63][m 64..80][one 81][xc 82..98][pad 99..111]

typedef unsigned int u32;

__device__ float g_num[T * NB];
__device__ float g_den[T * NB];
__device__ unsigned int g_cnt;

// ---- smem byte offsets ----
#define SM_BHI   0          // 256*240 = 61440
#define SM_BLO   61440
#define SM_A0    122880     // 2 buffers x (hi+lo) = 61440
#define SM_WRGH  184320     // 24*144 = 3456
#define SM_WRGL  187776
#define SM_X     191232     // [2][64][17] f32 = 8704
#define SM_M     199936     // 8704
#define SM_D     208640     // [2][64][20] f32 = 10240
#define SM_WTD   218880     // [64][20] f32 = 5120
#define SM_WOUT  224000
#define SM_BTD   224256
#define SM_BREG  224512
#define SM_Y     224608     // 64*8*4 = 2048
#define SM_RED   226656
#define SM_SV    226784
#define SM_BOUT  227040
#define SM_FLAG  227044
#define SM_TOTAL 227072

__device__ __forceinline__ u32 smem_u32(const void* p) {
    u32 a;
    asm("{ .reg .u64 t; cvta.to.shared.u64 t, %1; cvt.u32.u64 %0, t; }" : "=r"(a) : "l"(p));
    return a;
}
__device__ __forceinline__ float tanhax(float x) {
    float r;
    asm("tanh.approx.f32 %0, %1;" : "=f"(r) : "f"(x));
    return r;
}
__device__ __forceinline__ float sigm(float x) {
    return fmaf(0.5f, tanhax(0.5f * x), 0.5f);
}
__device__ __forceinline__ u32 pk_hi(float a, float b) {
    return (u32)__bfloat16_as_ushort(__float2bfloat16(a)) |
           ((u32)__bfloat16_as_ushort(__float2bfloat16(b)) << 16);
}
__device__ __forceinline__ u32 pk_lo(float a, float b) {
    float ra = a - __bfloat162float(__float2bfloat16(a));
    float rb = b - __bfloat162float(__float2bfloat16(b));
    return pk_hi(ra, rb);
}

#define LDSM4(r, addr) \
    asm volatile("ldmatrix.sync.aligned.m8n8.x4.shared.b16 {%0,%1,%2,%3}, [%4];" \
        : "=r"((r)[0]), "=r"((r)[1]), "=r"((r)[2]), "=r"((r)[3]) : "r"(addr))
#define LDSM2(r, addr) \
    asm volatile("ldmatrix.sync.aligned.m8n8.x2.shared.b16 {%0,%1}, [%2];" \
        : "=r"((r)[0]), "=r"((r)[1]) : "r"(addr))

#define MMA16816(c, a, b0, b1) \
    asm volatile("mma.sync.aligned.m16n8k16.row.col.f32.bf16.bf16.f32 " \
        "{%0,%1,%2,%3}, {%4,%5,%6,%7}, {%8,%9}, {%0,%1,%2,%3};" \
        : "+f"((c)[0]), "+f"((c)[1]), "+f"((c)[2]), "+f"((c)[3]) \
        : "r"((a)[0]), "r"((a)[1]), "r"((a)[2]), "r"((a)[3]), "r"(b0), "r"(b1))

#define STS128(addr, r0, r1, r2, r3) \
    asm volatile("st.shared.v4.b32 [%0], {%1,%2,%3,%4};" \
        :: "r"(addr), "r"(r0), "r"(r1), "r"(r2), "r"(r3) : "memory")

__global__ void __launch_bounds__(NTHREADS, 1)
grud_kernel(const float* __restrict__ values,
            const float* __restrict__ masks,
            const float* __restrict__ deltas,
            const float* __restrict__ Wtd, const float* __restrict__ btd,
            const float* __restrict__ Wreg, const float* __restrict__ breg,
            const float* __restrict__ Wih, const float* __restrict__ Whh,
            const float* __restrict__ bih, const float* __restrict__ bhh,
            const float* __restrict__ Wout, const float* __restrict__ bout,
            float* __restrict__ out_loss,
            float* __restrict__ out_imp,
            float* __restrict__ out_yh)
{
    extern __shared__ __align__(128) char smem[];
    const u32 sbase = smem_u32(smem);
    float* sX    = (float*)(smem + SM_X);     // [2][64][17]
    float* sM    = (float*)(smem + SM_M);
    float* sD    = (float*)(smem + SM_D);     // [2][64][20]
    float* sWtd  = (float*)(smem + SM_WTD);   // [64][20]
    float* sWout = (float*)(smem + SM_WOUT);
    float* sBtd  = (float*)(smem + SM_BTD);
    float* sBreg = (float*)(smem + SM_BREG);
    float* sY    = (float*)(smem + SM_Y);     // [64][8]
    float* sRed  = (float*)(smem + SM_RED);
    float* sSv   = (float*)(smem + SM_SV);
    float* sBout = (float*)(smem + SM_BOUT);
    int*   sFlag = (int*)(smem + SM_FLAG);

    const int tid = threadIdx.x;
    const int wid = tid >> 5;
    const int lid = tid & 31;
    const int wm = wid & 1;              // gates M tile: rows wm*32 .. +31
    const int wn = wid >> 1;             // gates N group: 32 gate-cols = hids wn*8..+7
    const int xwm = wid & 3;             // x_h M tile: rows xwm*16 .. +15
    const int xwn = wid >> 2;            // x_h f-group (0..2 active)
    const int hsel = (lid & 3) >> 1;
    const int rpar = lid & 1;
    const int myrow = wm * 32 + (lid >> 2) + rpar * 8;   // first gates m16 tile row
    const int bb = blockIdx.x * BT;

    // ---- prezero both A buffers (hi+lo) and Wreg tiles ----
    for (int i = tid; i < (2 * ABUF_SZ) / 4; i += NTHREADS)
        ((u32*)(smem + SM_A0))[i] = 0u;
    for (int i = tid; i < (24 * 144) / 4; i += NTHREADS) {
        ((u32*)(smem + SM_WRGH))[i] = 0u;
        ((u32*)(smem + SM_WRGL))[i] = 0u;
    }
    // ---- build gates B hi/lo tiles: [n][k], n = hid*4 + gate ----
    for (int i = tid; i < 256 * 112; i += NTHREADS) {
        int n = i / 112, k = i % 112;
        int out = (n & 3) * 64 + (n >> 2);
        float w = 0.0f;
        if (k < 64)       w = Whh[out * 64 + k];
        else if (k < 81)  w = Wih[out * 34 + 17 + (k - 64)];  // m part
        else if (k == 81) w = bih[out] + bhh[out];            // bias (ones col)
        else if (k < 99)  w = Wih[out * 34 + (k - 82)];       // xc part
        __nv_bfloat16 whi = __float2bfloat16(w);
        float wlo = w - __bfloat162float(whi);
        *(__nv_bfloat16*)(smem + SM_BHI + n * BSTR + k * 2) = whi;
        *(__nv_bfloat16*)(smem + SM_BLO + n * BSTR + k * 2) = __float2bfloat16(wlo);
    }
    __syncthreads();
    // ---- Wreg^T hi/lo tile [f][k] ----
    for (int i = tid; i < F * HID; i += NTHREADS) {
        int f = i / HID, k = i % HID;
        float w = Wreg[f * HID + k];
        __nv_bfloat16 whi = __float2bfloat16(w);
        *(__nv_bfloat16*)(smem + SM_WRGH + f * 144 + k * 2) = whi;
        *(__nv_bfloat16*)(smem + SM_WRGL + f * 144 + k * 2) =
            __float2bfloat16(w - __bfloat162float(whi));
    }
    for (int i = tid; i < HID * F; i += NTHREADS) {
        int h = i / F, k = i % F;
        sWtd[h * 20 + k] = Wtd[h * F + k];
    }
    if (tid < HID) sBtd[tid] = btd[tid];
    if (tid < F)   sBreg[tid] = breg[tid];
    if (tid < HID) sWout[tid] = Wout[tid];
    if (tid == 0)  sBout[0] = bout[0];
    // ones column (k=81 -> byte 162), both buffers
    if (tid < BT) {
        *(__nv_bfloat16*)(smem + SM_A0 + tid * BSTR + 162) = __float2bfloat16(1.0f);
        *(__nv_bfloat16*)(smem + SM_A0 + ABUF_SZ + tid * BSTR + 162) = __float2bfloat16(1.0f);
    }
    // t=0 inputs -> buffer 0 (+ m bf16 cols into A buf0)
    for (int o = tid; o < BT * F; o += NTHREADS) {
        int r = o / F, f = o % F;
        int base = (bb + r) * (T * F) + f;
        float xv = values[base];
        xv = (xv != xv) ? 0.0f : xv;
        float mv = masks[base];
        sX[r * 17 + f] = xv;
        sM[r * 17 + f] = mv;
        sD[r * 20 + f] = deltas[base];
        *(__nv_bfloat16*)(smem + SM_A0 + r * BSTR + 128 + 2 * f) = __float2bfloat16(mv);
    }
    __syncthreads();

    // ---- ldmatrix lane address bases (buffer 0) ----
    const u32 aHiBase = sbase + SM_A0 +
        (u32)((wm * 32 + (lid & 7) + ((lid >> 3) & 1) * 8) * BSTR + ((lid >> 4) & 1) * 16);
    const u32 axHiBase = sbase + SM_A0 +
        (u32)((xwm * 16 + (lid & 7) + ((lid >> 3) & 1) * 8) * BSTR + ((lid >> 4) & 1) * 16);
    const u32 bHiAddr = sbase + SM_BHI +
        (u32)((wn * 32 + ((lid >> 4) & 1) * 8 + (lid & 7)) * BSTR + ((lid >> 3) & 1) * 16);
    const u32 bLoAddr = bHiAddr + (SM_BLO - SM_BHI);
    const u32 wrgHAddr = sbase + SM_WRGH +
        (u32)((xwn * 8 + (lid & 7)) * 144 + ((lid >> 3) & 1) * 16);
    const u32 wrgLAddr = wrgHAddr + (SM_WRGL - SM_WRGH);

    // ---- hoisted prefetch indices ----
    int prR[3], prF[3], prB[3];
    #pragma unroll
    for (int j = 0; j < 3; j++) {
        int o = tid + j * NTHREADS;
        int r = o / F, f = o - r * F;
        prR[j] = r; prF[j] = f;
        prB[j] = (bb + r) * (T * F) + f;
    }
    const bool pf3 = (tid < BT * F - 2 * NTHREADS);

    // state: h_reg[mt*4+nt] <-> (row myrow+mt*16, hid wn*8+nt*2+hsel)
    float h_reg[8], c_reg[8];
    #pragma unroll
    for (int i = 0; i < 8; i++) { h_reg[i] = 0.0f; c_reg[i] = 0.0f; }

    for (int t = 0; t < T; t++) {
        const int cur = t & 1;
        const int nxt = cur ^ 1;
        const u32 curA = (u32)cur * ABUF_SZ;
        const u32 nxtA = (u32)nxt * ABUF_SZ;
        const u32 aHiAddr = aHiBase + curA;
        const u32 aLoAddr = aHiAddr + 15360;
        const u32 axHiAddr = axHiBase + curA;
        const u32 axLoAddr = axHiAddr + 15360;

        // ---- prefetch t+1 into registers ----
        float pX[3], pM[3], pD[3];
        if (t + 1 < T) {
            #pragma unroll
            for (int j = 0; j < 2; j++) {
                int base = prB[j] + (t + 1) * F;
                pX[j] = values[base]; pM[j] = masks[base]; pD[j] = deltas[base];
            }
            if (pf3) {
                int base = prB[2] + (t + 1) * F;
                pX[2] = values[base]; pM[2] = masks[base]; pD[2] = deltas[base];
            }
        }

        // ---- phase 2: gamma, hd = h*gamma -> A[cur] h-cols (k 0..63) ----
        {
            const float* dvp0 = &sD[cur * 1280 + myrow * 20];
            const float* dvp1 = dvp0 + 16 * 20;
            float4 a0 = *(const float4*)&dvp0[0];
            float4 a1 = *(const float4*)&dvp0[4];
            float4 a2 = *(const float4*)&dvp0[8];
            float4 a3 = *(const float4*)&dvp0[12];
            float  a16 = dvp0[16];
            float4 b0 = *(const float4*)&dvp1[0];
            float4 b1 = *(const float4*)&dvp1[4];
            float4 b2 = *(const float4*)&dvp1[8];
            float4 b3 = *(const float4*)&dvp1[12];
            float  b16 = dvp1[16];
            u32 whi0[4], wlo0[4], whi1[4], wlo1[4];
            #pragma unroll
            for (int nt = 0; nt < 4; nt++) {
                int hid = wn * 8 + nt * 2 + hsel;
                const float* wt = &sWtd[hid * 20];
                float4 w0 = *(const float4*)&wt[0];
                float4 w1 = *(const float4*)&wt[4];
                float4 w2 = *(const float4*)&wt[8];
                float4 w3 = *(const float4*)&wt[12];
                float wb = sBtd[hid];
                float w16 = wt[16];
                float acc0 = wb + a16 * w16;
                acc0 += a0.x*w0.x + a0.y*w0.y + a0.z*w0.z + a0.w*w0.w;
                acc0 += a1.x*w1.x + a1.y*w1.y + a1.z*w1.z + a1.w*w1.w;
                acc0 += a2.x*w2.x + a2.y*w2.y + a2.z*w2.z + a2.w*w2.w;
                acc0 += a3.x*w3.x + a3.y*w3.y + a3.z*w3.z + a3.w*w3.w;
                float acc1 = wb + b16 * w16;
                acc1 += b0.x*w0.x + b0.y*w0.y + b0.z*w0.z + b0.w*w0.w;
                acc1 += b1.x*w1.x + b1.y*w1.y + b1.z*w1.z + b1.w*w1.w;
                acc1 += b2.x*w2.x + b2.y*w2.y + b2.z*w2.z + b2.w*w2.w;
                acc1 += b3.x*w3.x + b3.y*w3.y + b3.z*w3.z + b3.w*w3.w;
                float hd0 = h_reg[nt]     * __expf(-fmaxf(acc0, 0.0f));
                float hd1 = h_reg[4 + nt] * __expf(-fmaxf(acc1, 0.0f));
                float hp0 = __shfl_xor_sync(0xFFFFFFFFu, hd0, 2);
                float hp1 = __shfl_xor_sync(0xFFFFFFFFu, hd1, 2);
                whi0[nt] = pk_hi(hd0, hp0);
                wlo0[nt] = pk_lo(hd0, hp0);
                whi1[nt] = pk_hi(hd1, hp1);
                wlo1[nt] = pk_lo(hd1, hp1);
            }
            if (hsel == 0) {
                u32 ad0 = sbase + SM_A0 + curA + (u32)(myrow * BSTR + wn * 16);
                u32 ad1 = ad0 + 16 * BSTR;
                STS128(ad0, whi0[0], whi0[1], whi0[2], whi0[3]);
                STS128(ad1, whi1[0], whi1[1], whi1[2], whi1[3]);
                STS128(ad0 + 15360, wlo0[0], wlo0[1], wlo0[2], wlo0[3]);
                STS128(ad1 + 15360, wlo1[0], wlo1[1], wlo1[2], wlo1[3]);
            }
        }
        __syncthreads();   // #1: A[cur] h-cols ready; prev phaseB complete everywhere

        // ==== phase A ====
        float cfr[8][4];
        #pragma unroll
        for (int i = 0; i < 8; i++)
            #pragma unroll
            for (int j = 0; j < 4; j++) cfr[i][j] = 0.0f;

        float lnum = 0.0f, lden = 0.0f;
        float cx[4] = {0.0f, 0.0f, 0.0f, 0.0f};

        if (xwn < 3) {
            // x_h MMA over h k-tiles 0..3 (m16 x n8, 12 warps)
            #pragma unroll
            for (int kt = 0; kt < 4; kt++) {
                u32 ah[4], al[4], bh2[2], bl2[2];
                LDSM4(ah, axHiAddr + kt * 32);
                LDSM4(al, axLoAddr + kt * 32);
                LDSM2(bh2, wrgHAddr + kt * 32);
                LDSM2(bl2, wrgLAddr + kt * 32);
                MMA16816(cx, ah, bh2[0], bh2[1]);
                MMA16816(cx, al, bh2[0], bh2[1]);
                MMA16816(cx, ah, bl2[0], bl2[1]);
            }
        }

        // gates kt0..3 (full 3 passes), m32 x n32
        #pragma unroll
        for (int kt = 0; kt < 4; kt++) {
            u32 ah0[4], ah1[4], al0[4], al1[4];
            u32 bh01[4], bh23[4], bl01[4], bl23[4];
            LDSM4(ah0, aHiAddr + kt * 32);
            LDSM4(ah1, aHiAddr + 16 * BSTR + kt * 32);
            LDSM4(al0, aLoAddr + kt * 32);
            LDSM4(al1, aLoAddr + 16 * BSTR + kt * 32);
            LDSM4(bh01, bHiAddr + kt * 32);
            LDSM4(bh23, bHiAddr + 16 * BSTR + kt * 32);
            LDSM4(bl01, bLoAddr + kt * 32);
            LDSM4(bl23, bLoAddr + 16 * BSTR + kt * 32);
            MMA16816(cfr[0], ah0, bh01[0], bh01[1]);
            MMA16816(cfr[1], ah0, bh01[2], bh01[3]);
            MMA16816(cfr[2], ah0, bh23[0], bh23[1]);
            MMA16816(cfr[3], ah0, bh23[2], bh23[3]);
            MMA16816(cfr[4], ah1, bh01[0], bh01[1]);
            MMA16816(cfr[5], ah1, bh01[2], bh01[3]);
            MMA16816(cfr[6], ah1, bh23[0], bh23[1]);
            MMA16816(cfr[7], ah1, bh23[2], bh23[3]);
            MMA16816(cfr[0], al0, bh01[0], bh01[1]);
            MMA16816(cfr[1], al0, bh01[2], bh01[3]);
            MMA16816(cfr[2], al0, bh23[0], bh23[1]);
            MMA16816(cfr[3], al0, bh23[2], bh23[3]);
            MMA16816(cfr[4], al1, bh01[0], bh01[1]);
            MMA16816(cfr[5], al1, bh01[2], bh01[3]);
            MMA16816(cfr[6], al1, bh23[0], bh23[1]);
            MMA16816(cfr[7], al1, bh23[2], bh23[3]);
            MMA16816(cfr[0], ah0, bl01[0], bl01[1]);
            MMA16816(cfr[1], ah0, bl01[2], bl01[3]);
            MMA16816(cfr[2], ah0, bl23[0], bl23[1]);
            MMA16816(cfr[3], ah0, bl23[2], bl23[3]);
            MMA16816(cfr[4], ah1, bl01[0], bl01[1]);
            MMA16816(cfr[5], ah1, bl01[2], bl01[3]);
            MMA16816(cfr[6], ah1, bl23[0], bl23[1]);
            MMA16816(cfr[7], ah1, bl23[2], bl23[3]);
        }
        // gates kt4 (m cols: A-lo structurally zero -> skip Alo pass)
        {
            u32 ah0[4], ah1[4], bh01[4], bh23[4], bl01[4], bl23[4];
            LDSM4(ah0, aHiAddr + 4 * 32);
            LDSM4(ah1, aHiAddr + 16 * BSTR + 4 * 32);
            LDSM4(bh01, bHiAddr + 4 * 32);
            LDSM4(bh23, bHiAddr + 16 * BSTR + 4 * 32);
            LDSM4(bl01, bLoAddr + 4 * 32);
            LDSM4(bl23, bLoAddr + 16 * BSTR + 4 * 32);
            MMA16816(cfr[0], ah0, bh01[0], bh01[1]);
            MMA16816(cfr[1], ah0, bh01[2], bh01[3]);
            MMA16816(cfr[2], ah0, bh23[0], bh23[1]);
            MMA16816(cfr[3], ah0, bh23[2], bh23[3]);
            MMA16816(cfr[4], ah1, bh01[0], bh01[1]);
            MMA16816(cfr[5], ah1, bh01[2], bh01[3]);
            MMA16816(cfr[6], ah1, bh23[0], bh23[1]);
            MMA16816(cfr[7], ah1, bh23[2], bh23[3]);
            MMA16816(cfr[0], ah0, bl01[0], bl01[1]);
            MMA16816(cfr[1], ah0, bl01[2], bl01[3]);
            MMA16816(cfr[2], ah0, bl23[0], bl23[1]);
            MMA16816(cfr[3], ah0, bl23[2], bl23[3]);
            MMA16816(cfr[4], ah1, bl01[0], bl01[1]);
            MMA16816(cfr[5], ah1, bl01[2], bl01[3]);
            MMA16816(cfr[6], ah1, bl23[0], bl23[1]);
            MMA16816(cfr[7], ah1, bl23[2], bl23[3]);
        }

        // x_h epilogue: xc, loss, imputation, write A[cur] xc-cols (k 82..98)
        if (xwn < 3) {
            int f0 = xwn * 8 + (lid & 3) * 2;
            if (f0 < 17) {
                #pragma unroll
                for (int half = 0; half < 2; half++) {
                    int r = xwm * 16 + (lid >> 2) + half * 8;
                    float acc0 = cx[2 * half] + sBreg[f0];
                    float xv0 = sX[cur * 1088 + r * 17 + f0];
                    float mv0 = sM[cur * 1088 + r * 17 + f0];
                    float xc0 = mv0 * xv0 + (1.0f - mv0) * acc0;
                    lnum += fabsf(xv0 - acc0) * mv0;
                    lden += mv0;
                    out_imp[(bb + r) * (T * F) + t * F + f0] = xc0;
                    float xc1 = 0.0f;
                    if (f0 < 16) {
                        float acc1 = cx[2 * half + 1] + sBreg[f0 + 1];
                        float xv1 = sX[cur * 1088 + r * 17 + f0 + 1];
                        float mv1 = sM[cur * 1088 + r * 17 + f0 + 1];
                        xc1 = mv1 * xv1 + (1.0f - mv1) * acc1;
                        lnum += fabsf(xv1 - acc1) * mv1;
                        lden += mv1;
                        out_imp[(bb + r) * (T * F) + t * F + f0 + 1] = xc1;
                    }
                    *(u32*)(smem + SM_A0 + curA + r * BSTR + 164 + 2 * f0) = pk_hi(xc0, xc1);
                    *(u32*)(smem + SM_A0 + curA + 15360 + r * BSTR + 164 + 2 * f0) = pk_lo(xc0, xc1);
                }
            }
        }
        #pragma unroll
        for (int ofs = 16; ofs > 0; ofs >>= 1) {
            lnum += __shfl_down_sync(0xFFFFFFFFu, lnum, ofs);
            lden += __shfl_down_sync(0xFFFFFFFFu, lden, ofs);
        }
        if (lid == 0) { sRed[wid] = lnum; sRed[NW + wid] = lden; }

        // ---- prefetch stores -> buffers[nxt] + A[nxt] m-cols (safe after sync#1) ----
        if (t + 1 < T) {
            #pragma unroll
            for (int j = 0; j < 3; j++) {
                if (j == 2 && !pf3) break;
                float xv = pX[j];
                xv = (xv != xv) ? 0.0f : xv;
                int r = prR[j], f = prF[j];
                sX[nxt * 1088 + r * 17 + f] = xv;
                sM[nxt * 1088 + r * 17 + f] = pM[j];
                sD[nxt * 1280 + r * 20 + f] = pD[j];
                *(__nv_bfloat16*)(smem + SM_A0 + nxtA + r * BSTR + 128 + 2 * f) =
                    __float2bfloat16(pM[j]);
            }
        }
        __syncthreads();   // #2: A[cur] complete (xc), nxt inputs visible, sRed ready
        if (tid == 0) {
            float n = 0.0f, d = 0.0f;
            #pragma unroll
            for (int i = 0; i < NW; i++) { n += sRed[i]; d += sRed[NW + i]; }
            g_num[t * NB + blockIdx.x] = n;
            g_den[t * NB + blockIdx.x] = d;
        }

        // ==== phase B: gates kt5..6 (xc-dependent) ====
        #pragma unroll
        for (int kt = 5; kt < 7; kt++) {
            u32 ah0[4], ah1[4], al0[4], al1[4];
            u32 bh01[4], bh23[4], bl01[4], bl23[4];
            LDSM4(ah0, aHiAddr + kt * 32);
            LDSM4(ah1, aHiAddr + 16 * BSTR + kt * 32);
            LDSM4(al0, aLoAddr + kt * 32);
            LDSM4(al1, aLoAddr + 16 * BSTR + kt * 32);
            LDSM4(bh01, bHiAddr + kt * 32);
            LDSM4(bh23, bHiAddr + 16 * BSTR + kt * 32);
            LDSM4(bl01, bLoAddr + kt * 32);
            LDSM4(bl23, bLoAddr + 16 * BSTR + kt * 32);
            MMA16816(cfr[0], ah0, bh01[0], bh01[1]);
            MMA16816(cfr[1], ah0, bh01[2], bh01[3]);
            MMA16816(cfr[2], ah0, bh23[0], bh23[1]);
            MMA16816(cfr[3], ah0, bh23[2], bh23[3]);
            MMA16816(cfr[4], ah1, bh01[0], bh01[1]);
            MMA16816(cfr[5], ah1, bh01[2], bh01[3]);
            MMA16816(cfr[6], ah1, bh23[0], bh23[1]);
            MMA16816(cfr[7], ah1, bh23[2], bh23[3]);
            MMA16816(cfr[0], al0, bh01[0], bh01[1]);
            MMA16816(cfr[1], al0, bh01[2], bh01[3]);
            MMA16816(cfr[2], al0, bh23[0], bh23[1]);
            MMA16816(cfr[3], al0, bh23[2], bh23[3]);
            MMA16816(cfr[4], al1, bh01[0], bh01[1]);
            MMA16816(cfr[5], al1, bh01[2], bh01[3]);
            MMA16816(cfr[6], al1, bh23[0], bh23[1]);
            MMA16816(cfr[7], al1, bh23[2], bh23[3]);
            MMA16816(cfr[0], ah0, bl01[0], bl01[1]);
            MMA16816(cfr[1], ah0, bl01[2], bl01[3]);
            MMA16816(cfr[2], ah0, bl23[0], bl23[1]);
            MMA16816(cfr[3], ah0, bl23[2], bl23[3]);
            MMA16816(cfr[4], ah1, bl01[0], bl01[1]);
            MMA16816(cfr[5], ah1, bl01[2], bl01[3]);
            MMA16816(cfr[6], ah1, bl23[0], bl23[1]);
            MMA16816(cfr[7], ah1, bl23[2], bl23[3]);
        }

        // ---- LSTM epilogue: tile = mt*4+nt (2-shfl exchange) ----
        #pragma unroll
        for (int tile = 0; tile < 8; tile++) {
            float v0 = rpar ? cfr[tile][0] : cfr[tile][2];
            float v1 = rpar ? cfr[tile][1] : cfr[tile][3];
            float e0 = __shfl_xor_sync(0xFFFFFFFFu, v0, 1);
            float e1 = __shfl_xor_sync(0xFFFFFFFFu, v1, 1);
            float gi, gf, gg, go;
            if (rpar == 0) { gi = cfr[tile][0]; gf = cfr[tile][1]; gg = e0; go = e1; }
            else           { gi = e0; gf = e1; gg = cfr[tile][2]; go = cfr[tile][3]; }
            float iv = sigm(gi), fv = sigm(gf);
            float gv = tanhax(gg), ov = sigm(go);
            float cc = fv * c_reg[tile] + iv * gv;
            c_reg[tile] = cc;
            h_reg[tile] = ov * tanhax(cc);
        }
    }

    // ---- y_h = h_final @ Wout^T + bout ----
    {
        float ph0 = 0.0f, ph1 = 0.0f;
        #pragma unroll
        for (int nt = 0; nt < 4; nt++) {
            float w = sWout[wn * 8 + nt * 2 + hsel];
            ph0 += h_reg[nt] * w;
            ph1 += h_reg[4 + nt] * w;
        }
        ph0 += __shfl_xor_sync(0xFFFFFFFFu, ph0, 2);
        ph1 += __shfl_xor_sync(0xFFFFFFFFu, ph1, 2);
        if (hsel == 0) {
            sY[myrow * 8 + wn] = ph0;
            sY[(myrow + 16) * 8 + wn] = ph1;
        }
    }
    __syncthreads();
    if (tid < BT) {
        float acc = sBout[0];
        #pragma unroll
        for (int i = 0; i < 8; i++) acc += sY[tid * 8 + i];
        out_yh[bb + tid] = acc;
    }

    // ---- folded finalize ----
    if (tid == 0) {
        __threadfence();
        unsigned int prev = atomicAdd(&g_cnt, 1u);
        sFlag[0] = (prev == NB - 1) ? 1 : 0;
    }
    __syncthreads();
    if (sFlag[0]) {
        __threadfence();
        float v = 0.0f;
        if (tid < T) {
            float n = 0.0f, d = 0.0f;
            for (int b = 0; b < NB; b++) {
                n += g_num[tid * NB + b];
                d += g_den[tid * NB + b];
            }
            v = n / (d + 1e-5f);
        }
        if (tid < 64) sSv[tid] = v;
        __syncthreads();
        if (tid < 32) {
            float x = sSv[tid] + sSv[tid + 32];
            #pragma unroll
            for (int ofs = 16; ofs > 0; ofs >>= 1)
                x += __shfl_down_sync(0xFFFFFFFFu, x, ofs);
            if (tid == 0) {
                out_loss[0] = x;
                g_cnt = 0;
            }
        }
    }
}

extern "C" void kernel_launch(void* const* d_in, const int* in_sizes, int n_in,
                              void* d_out, int out_size) {
    const float* values = (const float*)d_in[0];
    const float* masks  = (const float*)d_in[1];
    const float* deltas = (const float*)d_in[2];
    const float* Wtd    = (const float*)d_in[3];
    const float* btd    = (const float*)d_in[4];
    const float* Wreg   = (const float*)d_in[5];
    const float* breg   = (const float*)d_in[6];
    const float* Wih    = (const float*)d_in[7];
    const float* Whh    = (const float*)d_in[8];
    const float* bih    = (const float*)d_in[9];
    const float* bhh    = (const float*)d_in[10];
    const float* Wout   = (const float*)d_in[11];
    const float* bout   = (const float*)d_in[12];

    float* out = (float*)d_out;
    float* out_loss = out;
    float* out_imp  = out + 1;
    float* out_yh   = out + 1 + BATCH * T * F;

    cudaFuncSetAttribute(grud_kernel,
                         cudaFuncAttributeMaxDynamicSharedMemorySize, SM_TOTAL);
    grud_kernel<<<NB, NTHREADS, SM_TOTAL>>>(
        values, masks, deltas, Wtd, btd, Wreg, breg,
        Wih, Whh, bih, bhh, Wout, bout, out_loss, out_imp, out_yh);
}

// round 16
// speedup vs baseline: 1.1235x; 1.1235x over previous
#include <cuda_runtime.h>
#include <cuda_bf16.h>

#define BATCH 8192
#define T 50
#define F 17
#define HID 64
#define BT 64
#define NB (BATCH/BT)   // 128 blocks
#define NTHREADS 512
#define NW 16
#define BSTR 240        // bytes per bf16-tile row
#define ABUF_SZ 30720   // one A buffer: hi(15360) + lo(15360)

// k layout of A / gates-B: [h 0..63][m 64..80][one 81][xc 82..98][pad 99..111]

typedef unsigned int u32;

__device__ float g_num[T * NB];
__device__ float g_den[T * NB];
__device__ unsigned int g_cnt;

// ---- smem byte offsets ----
#define SM_BHI   0          // 256*240 = 61440
#define SM_BLO   61440
#define SM_A0    122880     // 2 buffers x (hi+lo) = 61440
#define SM_WRGH  184320     // 24*144 = 3456
#define SM_WRGL  187776
#define SM_X     191232     // [2][64][17] f32 = 8704
#define SM_M     199936     // 8704
#define SM_D     208640     // [2][64][20] f32 = 10240
#define SM_WTD   218880     // [64][20] f32 = 5120
#define SM_WOUT  224000
#define SM_BTD   224256
#define SM_BREG  224512
#define SM_Y     224608     // 64*8*4 = 2048
#define SM_RED   226656
#define SM_SV    226784
#define SM_BOUT  227040
#define SM_FLAG  227044
#define SM_TOTAL 227072

__device__ __forceinline__ u32 smem_u32(const void* p) {
    u32 a;
    asm("{ .reg .u64 t; cvta.to.shared.u64 t, %1; cvt.u32.u64 %0, t; }" : "=r"(a) : "l"(p));
    return a;
}
__device__ __forceinline__ float tanhax(float x) {
    float r;
    asm("tanh.approx.f32 %0, %1;" : "=f"(r) : "f"(x));
    return r;
}
__device__ __forceinline__ float sigm(float x) {
    return fmaf(0.5f, tanhax(0.5f * x), 0.5f);
}
__device__ __forceinline__ u32 pk_hi(float a, float b) {
    return (u32)__bfloat16_as_ushort(__float2bfloat16(a)) |
           ((u32)__bfloat16_as_ushort(__float2bfloat16(b)) << 16);
}
__device__ __forceinline__ u32 pk_lo(float a, float b) {
    float ra = a - __bfloat162float(__float2bfloat16(a));
    float rb = b - __bfloat162float(__float2bfloat16(b));
    return pk_hi(ra, rb);
}

#define LDSM4(r, addr) \
    asm volatile("ldmatrix.sync.aligned.m8n8.x4.shared.b16 {%0,%1,%2,%3}, [%4];" \
        : "=r"((r)[0]), "=r"((r)[1]), "=r"((r)[2]), "=r"((r)[3]) : "r"(addr))
#define LDSM2(r, addr) \
    asm volatile("ldmatrix.sync.aligned.m8n8.x2.shared.b16 {%0,%1}, [%2];" \
        : "=r"((r)[0]), "=r"((r)[1]) : "r"(addr))

#define MMA16816(c, a, b0, b1) \
    asm volatile("mma.sync.aligned.m16n8k16.row.col.f32.bf16.bf16.f32 " \
        "{%0,%1,%2,%3}, {%4,%5,%6,%7}, {%8,%9}, {%0,%1,%2,%3};" \
        : "+f"((c)[0]), "+f"((c)[1]), "+f"((c)[2]), "+f"((c)[3]) \
        : "r"((a)[0]), "r"((a)[1]), "r"((a)[2]), "r"((a)[3]), "r"(b0), "r"(b1))

#define STS128(addr, r0, r1, r2, r3) \
    asm volatile("st.shared.v4.b32 [%0], {%1,%2,%3,%4};" \
        :: "r"(addr), "r"(r0), "r"(r1), "r"(r2), "r"(r3) : "memory")

__global__ void __launch_bounds__(NTHREADS, 1)
grud_kernel(const float* __restrict__ values,
            const float* __restrict__ masks,
            const float* __restrict__ deltas,
            const float* __restrict__ Wtd, const float* __restrict__ btd,
            const float* __restrict__ Wreg, const float* __restrict__ breg,
            const float* __restrict__ Wih, const float* __restrict__ Whh,
            const float* __restrict__ bih, const float* __restrict__ bhh,
            const float* __restrict__ Wout, const float* __restrict__ bout,
            float* __restrict__ out_loss,
            float* __restrict__ out_imp,
            float* __restrict__ out_yh)
{
    extern __shared__ __align__(128) char smem[];
    const u32 sbase = smem_u32(smem);
    float* sX    = (float*)(smem + SM_X);     // [2][64][17]
    float* sM    = (float*)(smem + SM_M);
    float* sD    = (float*)(smem + SM_D);     // [2][64][20]
    float* sWtd  = (float*)(smem + SM_WTD);   // [64][20]
    float* sWout = (float*)(smem + SM_WOUT);
    float* sBtd  = (float*)(smem + SM_BTD);
    float* sBreg = (float*)(smem + SM_BREG);
    float* sY    = (float*)(smem + SM_Y);     // [64][8]
    float* sRed  = (float*)(smem + SM_RED);
    float* sSv   = (float*)(smem + SM_SV);
    float* sBout = (float*)(smem + SM_BOUT);
    int*   sFlag = (int*)(smem + SM_FLAG);

    const int tid = threadIdx.x;
    const int wid = tid >> 5;
    const int lid = tid & 31;
    const int wm = wid & 1;              // gates M tile: rows wm*32 .. +31
    const int wn = wid >> 1;             // gates N group: 32 gate-cols = hids wn*8..+7
    const int xwm = wid & 3;             // x_h M tile: rows xwm*16 .. +15
    const int xwn = wid >> 2;            // x_h f-group (0..2 active)
    const int hsel = (lid & 3) >> 1;
    const int rpar = lid & 1;
    const int myrow = wm * 32 + (lid >> 2) + rpar * 8;   // first gates m16 tile row
    const int bb = blockIdx.x * BT;

    // ---- prezero both A buffers (hi+lo) and Wreg tiles ----
    for (int i = tid; i < (2 * ABUF_SZ) / 4; i += NTHREADS)
        ((u32*)(smem + SM_A0))[i] = 0u;
    for (int i = tid; i < (24 * 144) / 4; i += NTHREADS) {
        ((u32*)(smem + SM_WRGH))[i] = 0u;
        ((u32*)(smem + SM_WRGL))[i] = 0u;
    }
    // ---- build gates B hi/lo tiles: [n][k], n = hid*4 + gate ----
    for (int i = tid; i < 256 * 112; i += NTHREADS) {
        int n = i / 112, k = i % 112;
        int out = (n & 3) * 64 + (n >> 2);
        float w = 0.0f;
        if (k < 64)       w = Whh[out * 64 + k];
        else if (k < 81)  w = Wih[out * 34 + 17 + (k - 64)];  // m part
        else if (k == 81) w = bih[out] + bhh[out];            // bias (ones col)
        else if (k < 99)  w = Wih[out * 34 + (k - 82)];       // xc part
        __nv_bfloat16 whi = __float2bfloat16(w);
        float wlo = w - __bfloat162float(whi);
        *(__nv_bfloat16*)(smem + SM_BHI + n * BSTR + k * 2) = whi;
        *(__nv_bfloat16*)(smem + SM_BLO + n * BSTR + k * 2) = __float2bfloat16(wlo);
    }
    __syncthreads();
    // ---- Wreg^T hi/lo tile [f][k] ----
    for (int i = tid; i < F * HID; i += NTHREADS) {
        int f = i / HID, k = i % HID;
        float w = Wreg[f * HID + k];
        __nv_bfloat16 whi = __float2bfloat16(w);
        *(__nv_bfloat16*)(smem + SM_WRGH + f * 144 + k * 2) = whi;
        *(__nv_bfloat16*)(smem + SM_WRGL + f * 144 + k * 2) =
            __float2bfloat16(w - __bfloat162float(whi));
    }
    for (int i = tid; i < HID * F; i += NTHREADS) {
        int h = i / F, k = i % F;
        sWtd[h * 20 + k] = Wtd[h * F + k];
    }
    if (tid < HID) sBtd[tid] = btd[tid];
    if (tid < F)   sBreg[tid] = breg[tid];
    if (tid < HID) sWout[tid] = Wout[tid];
    if (tid == 0)  sBout[0] = bout[0];
    // ones column (k=81 -> byte 162), both buffers
    if (tid < BT) {
        *(__nv_bfloat16*)(smem + SM_A0 + tid * BSTR + 162) = __float2bfloat16(1.0f);
        *(__nv_bfloat16*)(smem + SM_A0 + ABUF_SZ + tid * BSTR + 162) = __float2bfloat16(1.0f);
    }
    // t=0 inputs -> buffer 0 (+ m bf16 cols into A buf0)
    for (int o = tid; o < BT * F; o += NTHREADS) {
        int r = o / F, f = o % F;
        int base = (bb + r) * (T * F) + f;
        float xv = values[base];
        xv = (xv != xv) ? 0.0f : xv;
        float mv = masks[base];
        sX[r * 17 + f] = xv;
        sM[r * 17 + f] = mv;
        sD[r * 20 + f] = deltas[base];
        *(__nv_bfloat16*)(smem + SM_A0 + r * BSTR + 128 + 2 * f) = __float2bfloat16(mv);
    }
    __syncthreads();

    // ---- ldmatrix lane address bases (buffer 0) ----
    const u32 aHiBase = sbase + SM_A0 +
        (u32)((wm * 32 + (lid & 7) + ((lid >> 3) & 1) * 8) * BSTR + ((lid >> 4) & 1) * 16);
    const u32 axHiBase = sbase + SM_A0 +
        (u32)((xwm * 16 + (lid & 7) + ((lid >> 3) & 1) * 8) * BSTR + ((lid >> 4) & 1) * 16);
    const u32 bHiAddr = sbase + SM_BHI +
        (u32)((wn * 32 + ((lid >> 4) & 1) * 8 + (lid & 7)) * BSTR + ((lid >> 3) & 1) * 16);
    const u32 bLoAddr = bHiAddr + (SM_BLO - SM_BHI);
    const u32 wrgHAddr = sbase + SM_WRGH +
        (u32)((xwn * 8 + (lid & 7)) * 144 + ((lid >> 3) & 1) * 16);
    const u32 wrgLAddr = wrgHAddr + (SM_WRGL - SM_WRGH);

    // ---- hoisted prefetch indices ----
    int prR[3], prF[3], prB[3];
    #pragma unroll
    for (int j = 0; j < 3; j++) {
        int o = tid + j * NTHREADS;
        int r = o / F, f = o - r * F;
        prR[j] = r; prF[j] = f;
        prB[j] = (bb + r) * (T * F) + f;
    }
    const bool pf3 = (tid < BT * F - 2 * NTHREADS);

    // state: h_reg[mt*4+nt] <-> (row myrow+mt*16, hid wn*8+nt*2+hsel)
    float h_reg[8], c_reg[8];
    #pragma unroll
    for (int i = 0; i < 8; i++) { h_reg[i] = 0.0f; c_reg[i] = 0.0f; }

    for (int t = 0; t < T; t++) {
        const int cur = t & 1;
        const int nxt = cur ^ 1;
        const u32 curA = (u32)cur * ABUF_SZ;
        const u32 nxtA = (u32)nxt * ABUF_SZ;
        const u32 aHiAddr = aHiBase + curA;
        const u32 aLoAddr = aHiAddr + 15360;
        const u32 axHiAddr = axHiBase + curA;
        const u32 axLoAddr = axHiAddr + 15360;

        // ---- prefetch t+1 into registers ----
        float pX[3], pM[3], pD[3];
        if (t + 1 < T) {
            #pragma unroll
            for (int j = 0; j < 2; j++) {
                int base = prB[j] + (t + 1) * F;
                pX[j] = values[base]; pM[j] = masks[base]; pD[j] = deltas[base];
            }
            if (pf3) {
                int base = prB[2] + (t + 1) * F;
                pX[2] = values[base]; pM[2] = masks[base]; pD[2] = deltas[base];
            }
        }

        // ---- phase 2: gamma, hd = h*gamma -> A[cur] h-cols (k 0..63) ----
        {
            const float* dvp0 = &sD[cur * 1280 + myrow * 20];
            const float* dvp1 = dvp0 + 16 * 20;
            float4 a0 = *(const float4*)&dvp0[0];
            float4 a1 = *(const float4*)&dvp0[4];
            float4 a2 = *(const float4*)&dvp0[8];
            float4 a3 = *(const float4*)&dvp0[12];
            float  a16 = dvp0[16];
            float4 b0 = *(const float4*)&dvp1[0];
            float4 b1 = *(const float4*)&dvp1[4];
            float4 b2 = *(const float4*)&dvp1[8];
            float4 b3 = *(const float4*)&dvp1[12];
            float  b16 = dvp1[16];
            u32 whi0[4], wlo0[4], whi1[4], wlo1[4];
            #pragma unroll
            for (int nt = 0; nt < 4; nt++) {
                int hid = wn * 8 + nt * 2 + hsel;
                const float* wt = &sWtd[hid * 20];
                float4 w0 = *(const float4*)&wt[0];
                float4 w1 = *(const float4*)&wt[4];
                float4 w2 = *(const float4*)&wt[8];
                float4 w3 = *(const float4*)&wt[12];
                float wb = sBtd[hid];
                float w16 = wt[16];
                float acc0 = wb + a16 * w16;
                acc0 += a0.x*w0.x + a0.y*w0.y + a0.z*w0.z + a0.w*w0.w;
                acc0 += a1.x*w1.x + a1.y*w1.y + a1.z*w1.z + a1.w*w1.w;
                acc0 += a2.x*w2.x + a2.y*w2.y + a2.z*w2.z + a2.w*w2.w;
                acc0 += a3.x*w3.x + a3.y*w3.y + a3.z*w3.z + a3.w*w3.w;
                float acc1 = wb + b16 * w16;
                acc1 += b0.x*w0.x + b0.y*w0.y + b0.z*w0.z + b0.w*w0.w;
                acc1 += b1.x*w1.x + b1.y*w1.y + b1.z*w1.z + b1.w*w1.w;
                acc1 += b2.x*w2.x + b2.y*w2.y + b2.z*w2.z + b2.w*w2.w;
                acc1 += b3.x*w3.x + b3.y*w3.y + b3.z*w3.z + b3.w*w3.w;
                float hd0 = h_reg[nt]     * __expf(-fmaxf(acc0, 0.0f));
                float hd1 = h_reg[4 + nt] * __expf(-fmaxf(acc1, 0.0f));
                float hp0 = __shfl_xor_sync(0xFFFFFFFFu, hd0, 2);
                float hp1 = __shfl_xor_sync(0xFFFFFFFFu, hd1, 2);
                whi0[nt] = pk_hi(hd0, hp0);
                wlo0[nt] = pk_lo(hd0, hp0);
                whi1[nt] = pk_hi(hd1, hp1);
                wlo1[nt] = pk_lo(hd1, hp1);
            }
            if (hsel == 0) {
                u32 ad0 = sbase + SM_A0 + curA + (u32)(myrow * BSTR + wn * 16);
                u32 ad1 = ad0 + 16 * BSTR;
                STS128(ad0, whi0[0], whi0[1], whi0[2], whi0[3]);
                STS128(ad1, whi1[0], whi1[1], whi1[2], whi1[3]);
                STS128(ad0 + 15360, wlo0[0], wlo0[1], wlo0[2], wlo0[3]);
                STS128(ad1 + 15360, wlo1[0], wlo1[1], wlo1[2], wlo1[3]);
            }
        }
        __syncthreads();   // #1: A[cur] h-cols ready; prev phaseB complete everywhere

        // ==== phase A ====
        float cfr[8][4];
        #pragma unroll
        for (int i = 0; i < 8; i++)
            #pragma unroll
            for (int j = 0; j < 4; j++) cfr[i][j] = 0.0f;

        float lnum = 0.0f, lden = 0.0f;
        float cx[4] = {0.0f, 0.0f, 0.0f, 0.0f};

        if (xwn < 3) {
            // x_h MMA over h k-tiles 0..3 (m16 x n8, 12 warps)
            #pragma unroll
            for (int kt = 0; kt < 4; kt++) {
                u32 ah[4], al[4], bh2[2], bl2[2];
                LDSM4(ah, axHiAddr + kt * 32);
                LDSM4(al, axLoAddr + kt * 32);
                LDSM2(bh2, wrgHAddr + kt * 32);
                LDSM2(bl2, wrgLAddr + kt * 32);
                MMA16816(cx, ah, bh2[0], bh2[1]);
                MMA16816(cx, al, bh2[0], bh2[1]);
                MMA16816(cx, ah, bl2[0], bl2[1]);
            }
        }

        // gates kt0..3 (full 3 passes), m32 x n32
        #pragma unroll
        for (int kt = 0; kt < 4; kt++) {
            u32 ah0[4], ah1[4], al0[4], al1[4];
            u32 bh01[4], bh23[4], bl01[4], bl23[4];
            LDSM4(ah0, aHiAddr + kt * 32);
            LDSM4(ah1, aHiAddr + 16 * BSTR + kt * 32);
            LDSM4(al0, aLoAddr + kt * 32);
            LDSM4(al1, aLoAddr + 16 * BSTR + kt * 32);
            LDSM4(bh01, bHiAddr + kt * 32);
            LDSM4(bh23, bHiAddr + 16 * BSTR + kt * 32);
            LDSM4(bl01, bLoAddr + kt * 32);
            LDSM4(bl23, bLoAddr + 16 * BSTR + kt * 32);
            MMA16816(cfr[0], ah0, bh01[0], bh01[1]);
            MMA16816(cfr[1], ah0, bh01[2], bh01[3]);
            MMA16816(cfr[2], ah0, bh23[0], bh23[1]);
            MMA16816(cfr[3], ah0, bh23[2], bh23[3]);
            MMA16816(cfr[4], ah1, bh01[0], bh01[1]);
            MMA16816(cfr[5], ah1, bh01[2], bh01[3]);
            MMA16816(cfr[6], ah1, bh23[0], bh23[1]);
            MMA16816(cfr[7], ah1, bh23[2], bh23[3]);
            MMA16816(cfr[0], al0, bh01[0], bh01[1]);
            MMA16816(cfr[1], al0, bh01[2], bh01[3]);
            MMA16816(cfr[2], al0, bh23[0], bh23[1]);
            MMA16816(cfr[3], al0, bh23[2], bh23[3]);
            MMA16816(cfr[4], al1, bh01[0], bh01[1]);
            MMA16816(cfr[5], al1, bh01[2], bh01[3]);
            MMA16816(cfr[6], al1, bh23[0], bh23[1]);
            MMA16816(cfr[7], al1, bh23[2], bh23[3]);
            MMA16816(cfr[0], ah0, bl01[0], bl01[1]);
            MMA16816(cfr[1], ah0, bl01[2], bl01[3]);
            MMA16816(cfr[2], ah0, bl23[0], bl23[1]);
            MMA16816(cfr[3], ah0, bl23[2], bl23[3]);
            MMA16816(cfr[4], ah1, bl01[0], bl01[1]);
            MMA16816(cfr[5], ah1, bl01[2], bl01[3]);
            MMA16816(cfr[6], ah1, bl23[0], bl23[1]);
            MMA16816(cfr[7], ah1, bl23[2], bl23[3]);
        }
        // gates kt4 (m cols: A-lo structurally zero -> skip Alo pass)
        {
            u32 ah0[4], ah1[4], bh01[4], bh23[4], bl01[4], bl23[4];
            LDSM4(ah0, aHiAddr + 4 * 32);
            LDSM4(ah1, aHiAddr + 16 * BSTR + 4 * 32);
            LDSM4(bh01, bHiAddr + 4 * 32);
            LDSM4(bh23, bHiAddr + 16 * BSTR + 4 * 32);
            LDSM4(bl01, bLoAddr + 4 * 32);
            LDSM4(bl23, bLoAddr + 16 * BSTR + 4 * 32);
            MMA16816(cfr[0], ah0, bh01[0], bh01[1]);
            MMA16816(cfr[1], ah0, bh01[2], bh01[3]);
            MMA16816(cfr[2], ah0, bh23[0], bh23[1]);
            MMA16816(cfr[3], ah0, bh23[2], bh23[3]);
            MMA16816(cfr[4], ah1, bh01[0], bh01[1]);
            MMA16816(cfr[5], ah1, bh01[2], bh01[3]);
            MMA16816(cfr[6], ah1, bh23[0], bh23[1]);
            MMA16816(cfr[7], ah1, bh23[2], bh23[3]);
            MMA16816(cfr[0], ah0, bl01[0], bl01[1]);
            MMA16816(cfr[1], ah0, bl01[2], bl01[3]);
            MMA16816(cfr[2], ah0, bl23[0], bl23[1]);
            MMA16816(cfr[3], ah0, bl23[2], bl23[3]);
            MMA16816(cfr[4], ah1, bl01[0], bl01[1]);
            MMA16816(cfr[5], ah1, bl01[2], bl01[3]);
            MMA16816(cfr[6], ah1, bl23[0], bl23[1]);
            MMA16816(cfr[7], ah1, bl23[2], bl23[3]);
        }

        // x_h epilogue: xc, loss, imputation, write A[cur] xc-cols (k 82..98)
        if (xwn < 3) {
            int f0 = xwn * 8 + (lid & 3) * 2;
            if (f0 < 17) {
                #pragma unroll
                for (int half = 0; half < 2; half++) {
                    int r = xwm * 16 + (lid >> 2) + half * 8;
                    float acc0 = cx[2 * half] + sBreg[f0];
                    float xv0 = sX[cur * 1088 + r * 17 + f0];
                    float mv0 = sM[cur * 1088 + r * 17 + f0];
                    float xc0 = mv0 * xv0 + (1.0f - mv0) * acc0;
                    lnum += fabsf(xv0 - acc0) * mv0;
                    lden += mv0;
                    out_imp[(bb + r) * (T * F) + t * F + f0] = xc0;
                    float xc1 = 0.0f;
                    if (f0 < 16) {
                        float acc1 = cx[2 * half + 1] + sBreg[f0 + 1];
                        float xv1 = sX[cur * 1088 + r * 17 + f0 + 1];
                        float mv1 = sM[cur * 1088 + r * 17 + f0 + 1];
                        xc1 = mv1 * xv1 + (1.0f - mv1) * acc1;
                        lnum += fabsf(xv1 - acc1) * mv1;
                        lden += mv1;
                        out_imp[(bb + r) * (T * F) + t * F + f0 + 1] = xc1;
                    }
                    *(u32*)(smem + SM_A0 + curA + r * BSTR + 164 + 2 * f0) = pk_hi(xc0, xc1);
                    *(u32*)(smem + SM_A0 + curA + 15360 + r * BSTR + 164 + 2 * f0) = pk_lo(xc0, xc1);
                }
            }
        }
        #pragma unroll
        for (int ofs = 16; ofs > 0; ofs >>= 1) {
            lnum += __shfl_down_sync(0xFFFFFFFFu, lnum, ofs);
            lden += __shfl_down_sync(0xFFFFFFFFu, lden, ofs);
        }
        if (lid == 0) { sRed[wid] = lnum; sRed[NW + wid] = lden; }

        // ---- prefetch stores -> buffers[nxt] + A[nxt] m-cols (safe after sync#1) ----
        if (t + 1 < T) {
            #pragma unroll
            for (int j = 0; j < 3; j++) {
                if (j == 2 && !pf3) break;
                float xv = pX[j];
                xv = (xv != xv) ? 0.0f : xv;
                int r = prR[j], f = prF[j];
                sX[nxt * 1088 + r * 17 + f] = xv;
                sM[nxt * 1088 + r * 17 + f] = pM[j];
                sD[nxt * 1280 + r * 20 + f] = pD[j];
                *(__nv_bfloat16*)(smem + SM_A0 + nxtA + r * BSTR + 128 + 2 * f) =
                    __float2bfloat16(pM[j]);
            }
        }
        __syncthreads();   // #2: A[cur] complete (xc), nxt inputs visible, sRed ready
        if (tid == 0) {
            float n = 0.0f, d = 0.0f;
            #pragma unroll
            for (int i = 0; i < NW; i++) { n += sRed[i]; d += sRed[NW + i]; }
            g_num[t * NB + blockIdx.x] = n;
            g_den[t * NB + blockIdx.x] = d;
        }

        // ==== phase B: gates kt5..6 (xc-dependent) ====
        #pragma unroll
        for (int kt = 5; kt < 7; kt++) {
            u32 ah0[4], ah1[4], al0[4], al1[4];
            u32 bh01[4], bh23[4], bl01[4], bl23[4];
            LDSM4(ah0, aHiAddr + kt * 32);
            LDSM4(ah1, aHiAddr + 16 * BSTR + kt * 32);
            LDSM4(al0, aLoAddr + kt * 32);
            LDSM4(al1, aLoAddr + 16 * BSTR + kt * 32);
            LDSM4(bh01, bHiAddr + kt * 32);
            LDSM4(bh23, bHiAddr + 16 * BSTR + kt * 32);
            LDSM4(bl01, bLoAddr + kt * 32);
            LDSM4(bl23, bLoAddr + 16 * BSTR + kt * 32);
            MMA16816(cfr[0], ah0, bh01[0], bh01[1]);
            MMA16816(cfr[1], ah0, bh01[2], bh01[3]);
            MMA16816(cfr[2], ah0, bh23[0], bh23[1]);
            MMA16816(cfr[3], ah0, bh23[2], bh23[3]);
            MMA16816(cfr[4], ah1, bh01[0], bh01[1]);
            MMA16816(cfr[5], ah1, bh01[2], bh01[3]);
            MMA16816(cfr[6], ah1, bh23[0], bh23[1]);
            MMA16816(cfr[7], ah1, bh23[2], bh23[3]);
            MMA16816(cfr[0], al0, bh01[0], bh01[1]);
            MMA16816(cfr[1], al0, bh01[2], bh01[3]);
            MMA16816(cfr[2], al0, bh23[0], bh23[1]);
            MMA16816(cfr[3], al0, bh23[2], bh23[3]);
            MMA16816(cfr[4], al1, bh01[0], bh01[1]);
            MMA16816(cfr[5], al1, bh01[2], bh01[3]);
            MMA16816(cfr[6], al1, bh23[0], bh23[1]);
            MMA16816(cfr[7], al1, bh23[2], bh23[3]);
            MMA16816(cfr[0], ah0, bl01[0], bl01[1]);
            MMA16816(cfr[1], ah0, bl01[2], bl01[3]);
            MMA16816(cfr[2], ah0, bl23[0], bl23[1]);
            MMA16816(cfr[3], ah0, bl23[2], bl23[3]);
            MMA16816(cfr[4], ah1, bl01[0], bl01[1]);
            MMA16816(cfr[5], ah1, bl01[2], bl01[3]);
            MMA16816(cfr[6], ah1, bl23[0], bl23[1]);
            MMA16816(cfr[7], ah1, bl23[2], bl23[3]);
        }

        // ---- LSTM epilogue: tile = mt*4+nt ----
        #pragma unroll
        for (int tile = 0; tile < 8; tile++) {
            float e0 = __shfl_xor_sync(0xFFFFFFFFu, cfr[tile][0], 1);
            float e1 = __shfl_xor_sync(0xFFFFFFFFu, cfr[tile][1], 1);
            float e2 = __shfl_xor_sync(0xFFFFFFFFu, cfr[tile][2], 1);
            float e3 = __shfl_xor_sync(0xFFFFFFFFu, cfr[tile][3], 1);
            float gi, gf, gg, go;
            if (rpar == 0) { gi = cfr[tile][0]; gf = cfr[tile][1]; gg = e0; go = e1; }
            else           { gi = e2; gf = e3; gg = cfr[tile][2]; go = cfr[tile][3]; }
            float iv = sigm(gi), fv = sigm(gf);
            float gv = tanhax(gg), ov = sigm(go);
            float cc = fv * c_reg[tile] + iv * gv;
            c_reg[tile] = cc;
            h_reg[tile] = ov * tanhax(cc);
        }
    }

    // ---- y_h = h_final @ Wout^T + bout ----
    {
        float ph0 = 0.0f, ph1 = 0.0f;
        #pragma unroll
        for (int nt = 0; nt < 4; nt++) {
            float w = sWout[wn * 8 + nt * 2 + hsel];
            ph0 += h_reg[nt] * w;
            ph1 += h_reg[4 + nt] * w;
        }
        ph0 += __shfl_xor_sync(0xFFFFFFFFu, ph0, 2);
        ph1 += __shfl_xor_sync(0xFFFFFFFFu, ph1, 2);
        if (hsel == 0) {
            sY[myrow * 8 + wn] = ph0;
            sY[(myrow + 16) * 8 + wn] = ph1;
        }
    }
    __syncthreads();
    if (tid < BT) {
        float acc = sBout[0];
        #pragma unroll
        for (int i = 0; i < 8; i++) acc += sY[tid * 8 + i];
        out_yh[bb + tid] = acc;
    }

    // ---- folded finalize ----
    if (tid == 0) {
        __threadfence();
        unsigned int prev = atomicAdd(&g_cnt, 1u);
        sFlag[0] = (prev == NB - 1) ? 1 : 0;
    }
    __syncthreads();
    if (sFlag[0]) {
        __threadfence();
        float v = 0.0f;
        if (tid < T) {
            float n = 0.0f, d = 0.0f;
            for (int b = 0; b < NB; b++) {
                n += g_num[tid * NB + b];
                d += g_den[tid * NB + b];
            }
            v = n / (d + 1e-5f);
        }
        if (tid < 64) sSv[tid] = v;
        __syncthreads();
        if (tid < 32) {
            float x = sSv[tid] + sSv[tid + 32];
            #pragma unroll
            for (int ofs = 16; ofs > 0; ofs >>= 1)
                x += __shfl_down_sync(0xFFFFFFFFu, x, ofs);
            if (tid == 0) {
                out_loss[0] = x;
                g_cnt = 0;
            }
        }
    }
}

extern "C" void kernel_launch(void* const* d_in, const int* in_sizes, int n_in,
                              void* d_out, int out_size) {
    const float* values = (const float*)d_in[0];
    const float* masks  = (const float*)d_in[1];
    const float* deltas = (const float*)d_in[2];
    const float* Wtd    = (const float*)d_in[3];
    const float* btd    = (const float*)d_in[4];
    const float* Wreg   = (const float*)d_in[5];
    const float* breg   = (const float*)d_in[6];
    const float* Wih    = (const float*)d_in[7];
    const float* Whh    = (const float*)d_in[8];
    const float* bih    = (const float*)d_in[9];
    const float* bhh    = (const float*)d_in[10];
    const float* Wout   = (const float*)d_in[11];
    const float* bout   = (const float*)d_in[12];

    float* out = (float*)d_out;
    float* out_loss = out;
    float* out_imp  = out + 1;
    float* out_yh   = out + 1 + BATCH * T * F;

    cudaFuncSetAttribute(grud_kernel,
                         cudaFuncAttributeMaxDynamicSharedMemorySize, SM_TOTAL);
    grud_kernel<<<NB, NTHREADS, SM_TOTAL>>>(
        values, masks, deltas, Wtd, btd, Wreg, breg,
        Wih, Whh, bih, bhh, Wout, bout, out_loss, out_imp, out_yh);
}